// round 1
// baseline (speedup 1.0000x reference)
#include <cuda_runtime.h>
#include <math.h>

#define Bb    4
#define DIMC  192
#define Hh    256
#define Wc    256
#define NHEAD 6
#define WSZ   8
#define KBPE  32
#define HD    32
#define NTOK  64
#define NWIN  4096
#define TTOT  (Bb*Hh*Wc)   // 262144 tokens

typedef unsigned long long ull;

// ---------------- scratch (window-token layout [T, C]) ----------------
__device__ float g_xres[(size_t)TTOT*DIMC];     // shortcut (pre-LN x, NHWC window layout)
__device__ float g_xn  [(size_t)TTOT*DIMC];     // LN1 out; later reused for LN2 out
__device__ float g_bw  [(size_t)TTOT*KBPE];     // bpe window layout
__device__ float g_qkv [(size_t)TTOT*3*DIMC];   // [T, 576]
__device__ float g_bqk [(size_t)TTOT*2*DIMC];   // [T, 384]
__device__ float g_attn[(size_t)TTOT*DIMC];     // attention out; later reused for final
__device__ float g_xh2 [(size_t)TTOT*DIMC];     // residual after attention
__device__ float g_h1  [(size_t)TTOT*4*DIMC];   // fc1+gelu out [T, 768]

// ---------------- packed f32x2 helpers ----------------
__device__ __forceinline__ ull pack2(float x) {
    ull r; asm("mov.b64 %0, {%1, %1};" : "=l"(r) : "f"(x)); return r;
}
__device__ __forceinline__ void fma2(ull &d, ull a, ull b) {
    asm("fma.rn.f32x2 %0, %1, %2, %0;" : "+l"(d) : "l"(a), "l"(b));
}
__device__ __forceinline__ float2 unpack2(ull v) {
    float2 r; asm("mov.b64 {%0, %1}, %2;" : "=f"(r.x), "=f"(r.y) : "l"(v)); return r;
}

__device__ __forceinline__ float gelu_exact(float x) {
    return 0.5f * x * (1.0f + erff(x * 0.70710678118654752440f));
}

// =====================================================================
// K_pre: NCHW -> window layout transpose, LN1, bpe transpose
// grid (W/32, H, B), 256 threads
// =====================================================================
__global__ __launch_bounds__(256) void k_pre(
    const float* __restrict__ x, const float* __restrict__ bpe,
    const float* __restrict__ w1, const float* __restrict__ b1)
{
    __shared__ float xs[DIMC][33];
    __shared__ float bs[KBPE][33];
    __shared__ float smean[32], srstd[32];
    int w0 = blockIdx.x * 32, h = blockIdx.y, b = blockIdx.z;
    int tid = threadIdx.x, lane = tid & 31, wrp = tid >> 5;

    #pragma unroll
    for (int it = 0; it < 24; it++) {
        int c = it * 8 + wrp;
        xs[c][lane] = x[((size_t)(b*DIMC + c)*Hh + h)*Wc + w0 + lane];
    }
    #pragma unroll
    for (int it = 0; it < 4; it++) {
        int c = it * 8 + wrp;
        bs[c][lane] = bpe[((size_t)(b*KBPE + c)*Hh + h)*Wc + w0 + lane];
    }
    __syncthreads();

    // per-token LN stats: 8 threads per token
    int tok = tid >> 3, g = tid & 7;
    float s = 0.f, sq = 0.f;
    for (int c = g; c < DIMC; c += 8) { float v = xs[c][tok]; s += v; sq += v*v; }
    s  += __shfl_down_sync(0xffffffffu, s,  4, 8);
    sq += __shfl_down_sync(0xffffffffu, sq, 4, 8);
    s  += __shfl_down_sync(0xffffffffu, s,  2, 8);
    sq += __shfl_down_sync(0xffffffffu, sq, 2, 8);
    s  += __shfl_down_sync(0xffffffffu, s,  1, 8);
    sq += __shfl_down_sync(0xffffffffu, sq, 1, 8);
    if (g == 0) {
        float m = s * (1.0f/DIMC);
        float var = sq * (1.0f/DIMC) - m*m;
        smean[tok] = m;
        srstd[tok] = rsqrtf(var + 1e-5f);
    }
    __syncthreads();

    int whh = h >> 3, r = h & 7;
    #pragma unroll
    for (int it = 0; it < 24; it++) {
        int flat = it * 256 + tid;
        int tokj = flat / 192, c = flat - tokj * 192;
        int w = w0 + tokj, ww = w >> 3, cp = w & 7;
        int trow = ((b*32 + whh)*32 + ww)*64 + r*8 + cp;
        float v = xs[c][tokj];
        g_xres[(size_t)trow*DIMC + c] = v;
        g_xn  [(size_t)trow*DIMC + c] = (v - smean[tokj]) * srstd[tokj] * w1[c] + b1[c];
    }
    #pragma unroll
    for (int it = 0; it < 4; it++) {
        int flat = it * 256 + tid;
        int tokj = flat >> 5, c = flat & 31;
        int w = w0 + tokj, ww = w >> 3, cp = w & 7;
        int trow = ((b*32 + whh)*32 + ww)*64 + r*8 + cp;
        g_bw[(size_t)trow*KBPE + c] = bs[c][tokj];
    }
}

// =====================================================================
// SGEMM: C[M,N] = A[M,K] @ B[K,N] + bias, epilogue modes.
// BM=BN=128, BK=8, 256 threads, 8x8 tiles, packed f32x2 FMA.
// MODE 0: +bias ; MODE 1: +bias+res ; MODE 2: gelu(+bias)
// =====================================================================
template<int MODE>
__global__ __launch_bounds__(256) void sgemm128(
    const float* __restrict__ A, const float* __restrict__ Bm,
    const float* __restrict__ bias, const float* __restrict__ res,
    float* __restrict__ C, int M, int N, int Kd)
{
    __shared__ float As[8][128];
    __shared__ float Bs[8][128];
    int tid = threadIdx.x;
    int tx = tid & 15, ty = tid >> 4;
    int bx = blockIdx.x, by = blockIdx.y;

    int arow  = tid >> 1, acolb = (tid & 1) * 4;
    int brow  = tid >> 5, bcolb = (tid & 31) * 4;
    int bcol  = bx * 128 + bcolb;
    const float* Aptr = A + (size_t)(by*128 + arow) * Kd + acolb;

    ull acc[8][4];
    #pragma unroll
    for (int i = 0; i < 8; i++)
        #pragma unroll
        for (int j = 0; j < 4; j++) acc[i][j] = 0ULL;

    for (int kt = 0; kt < Kd; kt += 8) {
        float4 av = *(const float4*)(Aptr + kt);
        As[acolb+0][arow] = av.x;
        As[acolb+1][arow] = av.y;
        As[acolb+2][arow] = av.z;
        As[acolb+3][arow] = av.w;
        float4 bv = make_float4(0.f,0.f,0.f,0.f);
        if (bcol < N) bv = *(const float4*)(Bm + (size_t)(kt + brow) * N + bcol);
        *(float4*)&Bs[brow][bcolb] = bv;
        __syncthreads();

        #pragma unroll
        for (int kk = 0; kk < 8; kk++) {
            float4 a0 = *(const float4*)&As[kk][ty*8];
            float4 a1 = *(const float4*)&As[kk][ty*8+4];
            union { float4 f; ull u[2]; } ub0, ub1;
            ub0.f = *(const float4*)&Bs[kk][tx*8];
            ub1.f = *(const float4*)&Bs[kk][tx*8+4];
            ull bu0 = ub0.u[0], bu1 = ub0.u[1], bu2 = ub1.u[0], bu3 = ub1.u[1];
            float ar[8] = {a0.x,a0.y,a0.z,a0.w,a1.x,a1.y,a1.z,a1.w};
            #pragma unroll
            for (int i = 0; i < 8; i++) {
                ull a2 = pack2(ar[i]);
                fma2(acc[i][0], a2, bu0);
                fma2(acc[i][1], a2, bu1);
                fma2(acc[i][2], a2, bu2);
                fma2(acc[i][3], a2, bu3);
            }
        }
        __syncthreads();
    }

    #pragma unroll
    for (int i = 0; i < 8; i++) {
        int row = by*128 + ty*8 + i;
        #pragma unroll
        for (int jp = 0; jp < 4; jp++) {
            float2 v = unpack2(acc[i][jp]);
            int col = bx*128 + tx*8 + jp*2;
            #pragma unroll
            for (int sgm = 0; sgm < 2; sgm++) {
                int cc = col + sgm;
                if (cc < N) {
                    float o = (sgm == 0 ? v.x : v.y) + bias[cc];
                    if (MODE == 1) o += res[(size_t)row * N + cc];
                    if (MODE == 2) o = gelu_exact(o);
                    C[(size_t)row * N + cc] = o;
                }
            }
        }
    }
}

// =====================================================================
// K_attn: per (head, window). S = (QK^T + BqBk^T)*scale, softmax, P@V.
// grid (NHEAD, NWIN), 128 threads. 64x64x64 reg-tiled GEMM + 64x32x64.
// =====================================================================
__global__ __launch_bounds__(128) void k_attn()
{
    __shared__ float QT[64][68];   // [cc][i]: q (cc<32) | bq (cc>=32); reused as S[i][m]
    __shared__ float KT[64][68];   // [cc][j]: k | bk;                reused as P[m][i]
    __shared__ float VS[64][36];   // [m][j]
    __shared__ float rsum[64];

    int hd  = blockIdx.x;
    int win = blockIdx.y;
    int tid = threadIdx.x;
    int t0  = win * 64;
    int qo  = hd * 32;

    #pragma unroll
    for (int it = 0; it < 16; it++) {
        int flat = it * 128 + tid;
        int i = flat >> 5, c = flat & 31;
        size_t rq = (size_t)(t0 + i) * 576;
        size_t rb = (size_t)(t0 + i) * 384;
        QT[c][i]      = g_qkv[rq + qo + c];
        QT[32 + c][i] = g_bqk[rb + qo + c];
        KT[c][i]      = g_qkv[rq + 192 + qo + c];
        KT[32 + c][i] = g_bqk[rb + 192 + qo + c];
        VS[i][c]      = g_qkv[rq + 384 + qo + c];
    }
    __syncthreads();

    int tx = tid & 7, ty = tid >> 3;   // ty:0..15 rows i=ty*4.., tx cols j=tx*8..

    // ---- S = [Q|Bq] @ [K|Bk]^T over 64 inner dim ----
    ull acc[4][4];
    #pragma unroll
    for (int r = 0; r < 4; r++)
        #pragma unroll
        for (int j = 0; j < 4; j++) acc[r][j] = 0ULL;

    #pragma unroll 4
    for (int cc = 0; cc < 64; cc++) {
        float4 a4 = *(const float4*)&QT[cc][ty*4];
        union { float4 f; ull u[2]; } u0, u1;
        u0.f = *(const float4*)&KT[cc][tx*8];
        u1.f = *(const float4*)&KT[cc][tx*8+4];
        float ar[4] = {a4.x, a4.y, a4.z, a4.w};
        #pragma unroll
        for (int r = 0; r < 4; r++) {
            ull a2 = pack2(ar[r]);
            fma2(acc[r][0], a2, u0.u[0]);
            fma2(acc[r][1], a2, u0.u[1]);
            fma2(acc[r][2], a2, u1.u[0]);
            fma2(acc[r][3], a2, u1.u[1]);
        }
    }
    __syncthreads();   // all reads of QT/KT done

    const float scale = 0.17677669529663687f;  // 32^-0.5
    #pragma unroll
    for (int r = 0; r < 4; r++) {
        int i = ty*4 + r;
        #pragma unroll
        for (int jp = 0; jp < 4; jp++) {
            float2 v = unpack2(acc[r][jp]);
            int j = tx*8 + jp*2;
            QT[i][j]   = v.x * scale;   // S stored in QT
            QT[i][j+1] = v.y * scale;
        }
    }
    __syncthreads();

    // ---- softmax rows (2 threads per row) ----
    {
        int i = tid >> 1, half = tid & 1;
        int m0 = half * 32;
        float mx = -1e30f;
        #pragma unroll
        for (int m = 0; m < 32; m++) mx = fmaxf(mx, QT[i][m0 + m]);
        mx = fmaxf(mx, __shfl_xor_sync(0xffffffffu, mx, 1));
        float sm = 0.f;
        #pragma unroll
        for (int m = 0; m < 32; m++) {
            float p = expf(QT[i][m0 + m] - mx);
            sm += p;
            KT[m0 + m][i] = p;          // P transposed into KT: P[m][i]
        }
        sm += __shfl_xor_sync(0xffffffffu, sm, 1);
        if (half == 0) rsum[i] = 1.0f / sm;
    }
    __syncthreads();

    // ---- out = P @ V  (64x32x64) ----
    ull oacc[4][2];
    #pragma unroll
    for (int r = 0; r < 4; r++) { oacc[r][0] = 0ULL; oacc[r][1] = 0ULL; }

    #pragma unroll 4
    for (int m = 0; m < 64; m++) {
        float4 a4 = *(const float4*)&KT[m][ty*4];
        union { float4 f; ull u[2]; } uv;
        uv.f = *(const float4*)&VS[m][tx*4];
        float ar[4] = {a4.x, a4.y, a4.z, a4.w};
        #pragma unroll
        for (int r = 0; r < 4; r++) {
            ull a2 = pack2(ar[r]);
            fma2(oacc[r][0], a2, uv.u[0]);
            fma2(oacc[r][1], a2, uv.u[1]);
        }
    }

    #pragma unroll
    for (int r = 0; r < 4; r++) {
        int i = ty*4 + r;
        float rs = rsum[i];
        size_t ob = (size_t)(t0 + i) * 192 + qo + tx*4;
        float2 v0 = unpack2(oacc[r][0]);
        float2 v1 = unpack2(oacc[r][1]);
        g_attn[ob + 0] = v0.x * rs;
        g_attn[ob + 1] = v0.y * rs;
        g_attn[ob + 2] = v1.x * rs;
        g_attn[ob + 3] = v1.y * rs;
    }
}

// =====================================================================
// K_ln2: LN over g_xh2 -> g_xn. One warp per token.
// =====================================================================
__global__ __launch_bounds__(256) void k_ln2(
    const float* __restrict__ w2, const float* __restrict__ b2)
{
    int t = blockIdx.x * 8 + (threadIdx.x >> 5);
    int lane = threadIdx.x & 31;
    const float* rp = g_xh2 + (size_t)t * DIMC;
    float v[6];
    float s = 0.f, sq = 0.f;
    #pragma unroll
    for (int k = 0; k < 6; k++) {
        v[k] = rp[lane + k*32];
        s += v[k]; sq += v[k]*v[k];
    }
    #pragma unroll
    for (int off = 16; off > 0; off >>= 1) {
        s  += __shfl_xor_sync(0xffffffffu, s,  off);
        sq += __shfl_xor_sync(0xffffffffu, sq, off);
    }
    float m = s * (1.0f/DIMC);
    float var = sq * (1.0f/DIMC) - m*m;
    float rstd = rsqrtf(var + 1e-5f);
    float* op = g_xn + (size_t)t * DIMC;
    #pragma unroll
    for (int k = 0; k < 6; k++) {
        int c = lane + k*32;
        op[c] = (v[k] - m) * rstd * w2[c] + b2[c];
    }
}

// =====================================================================
// K_post: window layout -> NCHW output. grid (W/32, H, B), 256 threads.
// =====================================================================
__global__ __launch_bounds__(256) void k_post(float* __restrict__ out)
{
    __shared__ float os[DIMC][33];
    int w0 = blockIdx.x * 32, h = blockIdx.y, b = blockIdx.z;
    int tid = threadIdx.x, lane = tid & 31, wrp = tid >> 5;
    int whh = h >> 3, r = h & 7;

    #pragma unroll
    for (int it = 0; it < 24; it++) {
        int flat = it * 256 + tid;
        int tokj = flat / 192, c = flat - tokj * 192;
        int w = w0 + tokj, ww = w >> 3, cp = w & 7;
        int trow = ((b*32 + whh)*32 + ww)*64 + r*8 + cp;
        os[c][tokj] = g_attn[(size_t)trow*DIMC + c];
    }
    __syncthreads();
    #pragma unroll
    for (int it = 0; it < 24; it++) {
        int c = it * 8 + wrp;
        out[((size_t)(b*DIMC + c)*Hh + h)*Wc + w0 + lane] = os[c][lane];
    }
}

// =====================================================================
extern "C" void kernel_launch(void* const* d_in, const int* in_sizes, int n_in,
                              void* d_out, int out_size)
{
    const float* x     = (const float*)d_in[0];
    const float* bpe   = (const float*)d_in[1];
    const float* ln1w  = (const float*)d_in[2];
    const float* ln1b  = (const float*)d_in[3];
    const float* qkvw  = (const float*)d_in[4];
    const float* qkvb  = (const float*)d_in[5];
    const float* bpew  = (const float*)d_in[6];
    const float* bpeb  = (const float*)d_in[7];
    const float* projw = (const float*)d_in[8];
    const float* projb = (const float*)d_in[9];
    const float* ln2w  = (const float*)d_in[10];
    const float* ln2b  = (const float*)d_in[11];
    const float* fc1w  = (const float*)d_in[12];
    const float* fc1b  = (const float*)d_in[13];
    const float* fc2w  = (const float*)d_in[14];
    const float* fc2b  = (const float*)d_in[15];
    float* out = (float*)d_out;

    float *p_xres, *p_xn, *p_bw, *p_qkv, *p_bqk, *p_attn, *p_xh2, *p_h1;
    cudaGetSymbolAddress((void**)&p_xres, g_xres);
    cudaGetSymbolAddress((void**)&p_xn,   g_xn);
    cudaGetSymbolAddress((void**)&p_bw,   g_bw);
    cudaGetSymbolAddress((void**)&p_qkv,  g_qkv);
    cudaGetSymbolAddress((void**)&p_bqk,  g_bqk);
    cudaGetSymbolAddress((void**)&p_attn, g_attn);
    cudaGetSymbolAddress((void**)&p_xh2,  g_xh2);
    cudaGetSymbolAddress((void**)&p_h1,   g_h1);

    // 1. transpose + LN1 + bpe transpose
    k_pre<<<dim3(Wc/32, Hh, Bb), 256>>>(x, bpe, ln1w, ln1b);
    // 2. qkv = xn @ qkv_w + b          [T,192]x[192,576]
    sgemm128<0><<<dim3(5, TTOT/128), 256>>>(p_xn, qkvw, qkvb, nullptr, p_qkv, TTOT, 576, 192);
    // 3. bqk = bw @ bpe_w + b          [T,32]x[32,384]
    sgemm128<0><<<dim3(3, TTOT/128), 256>>>(p_bw, bpew, bpeb, nullptr, p_bqk, TTOT, 384, 32);
    // 4. attention per (head, window)
    k_attn<<<dim3(NHEAD, NWIN), 128>>>();
    // 5. xh2 = attn @ proj_w + b + shortcut
    sgemm128<1><<<dim3(2, TTOT/128), 256>>>(p_attn, projw, projb, p_xres, p_xh2, TTOT, 192, 192);
    // 6. LN2
    k_ln2<<<TTOT/8, 256>>>(ln2w, ln2b);
    // 7. h1 = gelu(xn @ fc1_w + b)     [T,192]x[192,768]
    sgemm128<2><<<dim3(6, TTOT/128), 256>>>(p_xn, fc1w, fc1b, nullptr, p_h1, TTOT, 768, 192);
    // 8. final = h1 @ fc2_w + b + xh2  [T,768]x[768,192]
    sgemm128<1><<<dim3(2, TTOT/128), 256>>>(p_h1, fc2w, fc2b, p_xh2, p_attn, TTOT, 192, 768);
    // 9. window layout -> NCHW
    k_post<<<dim3(Wc/32, Hh, Bb), 256>>>(out);
}

// round 5
// speedup vs baseline: 2.8601x; 2.8601x over previous
#include <cuda_runtime.h>
#include <cuda_bf16.h>
#include <math.h>
#include <stdint.h>

#define Bb    4
#define DIMC  192
#define Hh    256
#define Wc    256
#define NHEAD 6
#define KBPE  32
#define NWIN  4096
#define TTOT  (Bb*Hh*Wc)   // 262144 tokens

typedef unsigned long long ull;
typedef __nv_bfloat16 bf16;

// ---------------- scratch ----------------
__device__ float g_xres[(size_t)TTOT*DIMC];
__device__ bf16  g_xnh [(size_t)TTOT*DIMC];
__device__ bf16  g_xnl [(size_t)TTOT*DIMC];
__device__ bf16  g_bwh [(size_t)TTOT*KBPE];
__device__ bf16  g_bwl [(size_t)TTOT*KBPE];
__device__ float g_qkv [(size_t)TTOT*3*DIMC];
__device__ float g_bqk [(size_t)TTOT*2*DIMC];
__device__ bf16  g_ath [(size_t)TTOT*DIMC];
__device__ bf16  g_atl [(size_t)TTOT*DIMC];
__device__ float g_xh2 [(size_t)TTOT*DIMC];
__device__ bf16  g_h1h [(size_t)TTOT*4*DIMC];
__device__ bf16  g_h1l [(size_t)TTOT*4*DIMC];
// weights transposed [N,K], split hi/lo
__device__ bf16 g_wqh[576*192], g_wql[576*192];
__device__ bf16 g_wbh[384*32],  g_wbl[384*32];
__device__ bf16 g_wph[192*192], g_wpl[192*192];
__device__ bf16 g_w1h[768*192], g_w1l[768*192];
__device__ bf16 g_w2h[192*768], g_w2l[192*768];

// ---------------- helpers ----------------
__device__ __forceinline__ ull pack2(float x) {
    ull r; asm("mov.b64 %0, {%1, %1};" : "=l"(r) : "f"(x)); return r;
}
__device__ __forceinline__ void fma2(ull &d, ull a, ull b) {
    asm("fma.rn.f32x2 %0, %1, %2, %0;" : "+l"(d) : "l"(a), "l"(b));
}
__device__ __forceinline__ float2 unpack2(ull v) {
    float2 r; asm("mov.b64 {%0, %1}, %2;" : "=f"(r.x), "=f"(r.y) : "l"(v)); return r;
}
__device__ __forceinline__ float gelu_exact(float x) {
    return 0.5f * x * (1.0f + erff(x * 0.70710678118654752440f));
}
__device__ __forceinline__ uint32_t smem_u32(const void* p) {
    uint32_t a;
    asm("{ .reg .u64 t; cvta.to.shared.u64 t, %1; cvt.u32.u64 %0, t; }" : "=r"(a) : "l"(p));
    return a;
}
__device__ __forceinline__ void split_store(bf16* hi, bf16* lo, size_t idx, float v) {
    bf16 h = __float2bfloat16(v);
    hi[idx] = h;
    lo[idx] = __float2bfloat16(v - __bfloat162float(h));
}

// cp.async
__device__ __forceinline__ void cpa16(uint32_t dst, const void* src) {
    asm volatile("cp.async.ca.shared.global [%0], [%1], 16;" :: "r"(dst), "l"(src));
}
#define CP_COMMIT() asm volatile("cp.async.commit_group;" ::: "memory")
#define CP_WAIT1()  asm volatile("cp.async.wait_group 1;" ::: "memory")
#define CP_WAIT0()  asm volatile("cp.async.wait_group 0;" ::: "memory")

// ldmatrix (non-trans) x4
__device__ __forceinline__ void ldsm_x4(uint32_t* r, uint32_t addr) {
    asm volatile("ldmatrix.sync.aligned.m8n8.x4.shared.b16 {%0,%1,%2,%3}, [%4];"
        : "=r"(r[0]), "=r"(r[1]), "=r"(r[2]), "=r"(r[3]) : "r"(addr));
}
// bf16 mma m16n8k16, fp32 acc
__device__ __forceinline__ void mma_bf16(float* d, const uint32_t* a, const uint32_t* b) {
    asm volatile("mma.sync.aligned.m16n8k16.row.col.f32.bf16.bf16.f32 "
        "{%0,%1,%2,%3}, {%4,%5,%6,%7}, {%8,%9}, {%0,%1,%2,%3};"
        : "+f"(d[0]), "+f"(d[1]), "+f"(d[2]), "+f"(d[3])
        : "r"(a[0]), "r"(a[1]), "r"(a[2]), "r"(a[3]), "r"(b[0]), "r"(b[1]));
}

// =====================================================================
// k_wt: weight [K,N] fp32 -> [N,K] bf16 hi/lo
// =====================================================================
__global__ __launch_bounds__(256) void k_wt(const float* __restrict__ w,
                                            bf16* __restrict__ hi, bf16* __restrict__ lo,
                                            int K, int N)
{
    __shared__ float sm[32][33];
    int n0 = blockIdx.x * 32, k0 = blockIdx.y * 32;
    int tx = threadIdx.x, ty = threadIdx.y;
    #pragma unroll
    for (int j = 0; j < 32; j += 8)
        sm[ty + j][tx] = w[(size_t)(k0 + ty + j) * N + n0 + tx];
    __syncthreads();
    #pragma unroll
    for (int j = 0; j < 32; j += 8) {
        int n = n0 + ty + j, k = k0 + tx;
        split_store(hi, lo, (size_t)n * K + k, sm[tx][ty + j]);
    }
}

// =====================================================================
// k_pre: NCHW -> window layout, LN1 -> hi/lo planes, bpe -> hi/lo
// =====================================================================
__global__ __launch_bounds__(256) void k_pre(
    const float* __restrict__ x, const float* __restrict__ bpe,
    const float* __restrict__ w1, const float* __restrict__ b1)
{
    __shared__ float xs[DIMC][33];
    __shared__ float bs[KBPE][33];
    __shared__ float smean[32], srstd[32];
    int w0 = blockIdx.x * 32, h = blockIdx.y, b = blockIdx.z;
    int tid = threadIdx.x, lane = tid & 31, wrp = tid >> 5;

    #pragma unroll
    for (int it = 0; it < 24; it++) {
        int c = it * 8 + wrp;
        xs[c][lane] = x[((size_t)(b*DIMC + c)*Hh + h)*Wc + w0 + lane];
    }
    #pragma unroll
    for (int it = 0; it < 4; it++) {
        int c = it * 8 + wrp;
        bs[c][lane] = bpe[((size_t)(b*KBPE + c)*Hh + h)*Wc + w0 + lane];
    }
    __syncthreads();

    int tok = tid >> 3, g = tid & 7;
    float s = 0.f, sq = 0.f;
    for (int c = g; c < DIMC; c += 8) { float v = xs[c][tok]; s += v; sq += v*v; }
    s  += __shfl_down_sync(0xffffffffu, s, 4, 8);  sq += __shfl_down_sync(0xffffffffu, sq, 4, 8);
    s  += __shfl_down_sync(0xffffffffu, s, 2, 8);  sq += __shfl_down_sync(0xffffffffu, sq, 2, 8);
    s  += __shfl_down_sync(0xffffffffu, s, 1, 8);  sq += __shfl_down_sync(0xffffffffu, sq, 1, 8);
    if (g == 0) {
        float m = s * (1.0f/DIMC);
        float var = sq * (1.0f/DIMC) - m*m;
        smean[tok] = m;
        srstd[tok] = rsqrtf(var + 1e-5f);
    }
    __syncthreads();

    int whh = h >> 3, r = h & 7;
    #pragma unroll
    for (int it = 0; it < 24; it++) {
        int flat = it * 256 + tid;
        int tokj = flat / 192, c = flat - tokj * 192;
        int w = w0 + tokj, ww = w >> 3, cp = w & 7;
        int trow = ((b*32 + whh)*32 + ww)*64 + r*8 + cp;
        float v = xs[c][tokj];
        g_xres[(size_t)trow*DIMC + c] = v;
        float vn = (v - smean[tokj]) * srstd[tokj] * w1[c] + b1[c];
        split_store(g_xnh, g_xnl, (size_t)trow*DIMC + c, vn);
    }
    #pragma unroll
    for (int it = 0; it < 4; it++) {
        int flat = it * 256 + tid;
        int tokj = flat >> 5, c = flat & 31;
        int w = w0 + tokj, ww = w >> 3, cp = w & 7;
        int trow = ((b*32 + whh)*32 + ww)*64 + r*8 + cp;
        split_store(g_bwh, g_bwl, (size_t)trow*KBPE + c, bs[c][tokj]);
    }
}

// =====================================================================
// k_hmma: C = A @ W^T via mma.sync bf16 3-pass split.
// CTA 128x96, KC=16, 8 warps (4x2), warp 32x48 = 2x6 m16n8k16 tiles.
// smem stage (pitch 48B, 16B-aligned, conflict-free):
//   Ah[0..6144) Al[6144..12288) Bh[12288..16896) Bl[16896..21504)
// Double-buffered: 43008 B total (< 48KB, no attribute needed).
// MODE 0: +bias fp32 ; 1: +bias+res fp32 ; 2: gelu -> bf16 hi/lo
// =====================================================================
#define STAGE_B 21504
#define SMEM_HM (2*STAGE_B)

template<int MODE>
__global__ __launch_bounds__(256, 2) void k_hmma(
    const bf16* __restrict__ Ahi, const bf16* __restrict__ Alo,
    const bf16* __restrict__ Bhi, const bf16* __restrict__ Blo,
    const float* __restrict__ bias, const float* __restrict__ res,
    float* __restrict__ Cf, bf16* __restrict__ Chi, bf16* __restrict__ Clo,
    int N, int K)
{
    extern __shared__ char smc[];
    const uint32_t sb = smem_u32(smc);
    const int tid = threadIdx.x, lane = tid & 31, wid = tid >> 5;
    const int bx = blockIdx.x, by = blockIdx.y;
    const int mrow = (wid & 3) * 32, ncol = (wid >> 2) * 48;

    float acc[2][6][4];
    #pragma unroll
    for (int i = 0; i < 2; i++)
        #pragma unroll
        for (int j = 0; j < 6; j++)
            #pragma unroll
            for (int q = 0; q < 4; q++) acc[i][j][q] = 0.f;

    // ldmatrix lane address components
    const int a_row_l = ((lane >> 3) & 1) * 8 + (lane & 7);
    const int a_k_l   = (lane >> 4) * 8;
    const int b_n_l   = (lane >> 4) * 8 + (lane & 7);
    const int b_k_l   = ((lane >> 3) & 1) * 8;

    const int nt = K / 16;

    auto load_stage = [&](int s, int k0) {
        uint32_t base = sb + s * STAGE_B;
        // A: 128 rows x 16k, hi+lo => 512 chunks of 16B
        #pragma unroll
        for (int it = 0; it < 2; it++) {
            int id = it * 256 + tid;
            int pl = id >> 8, rem = id & 255;
            int row = rem >> 1, seg = rem & 1;
            const bf16* src = (pl ? Alo : Ahi) + (size_t)(by*128 + row) * K + k0 + seg*8;
            cpa16(base + pl*6144 + row*48 + seg*16, src);
        }
        // B: 96 rows x 16k, hi+lo => 384 chunks
        {
            int id = tid;                       // 0..255
            int pl = (id >= 192), rem = id - pl*192;
            int row = rem >> 1, seg = rem & 1;
            const bf16* src = (pl ? Blo : Bhi) + (size_t)(bx*96 + row) * K + k0 + seg*8;
            cpa16(base + 12288 + pl*4608 + row*48 + seg*16, src);
        }
        if (tid < 128) {
            int id = 256 + tid;                 // 256..383
            int pl = (id >= 192), rem = id - pl*192;
            int row = rem >> 1, seg = rem & 1;
            const bf16* src = (pl ? Blo : Bhi) + (size_t)(bx*96 + row) * K + k0 + seg*8;
            cpa16(base + 12288 + pl*4608 + row*48 + seg*16, src);
        }
        CP_COMMIT();
    };

    load_stage(0, 0);

    for (int t = 0; t < nt; t++) {
        if (t + 1 < nt) { load_stage((t + 1) & 1, (t + 1) * 16); CP_WAIT1(); }
        else            { CP_WAIT0(); }
        __syncthreads();

        uint32_t base = sb + (t & 1) * STAGE_B;
        uint32_t Ah[2][4], Al_[2][4], Bf[6][2];
        #pragma unroll
        for (int mt = 0; mt < 2; mt++) {
            uint32_t off = (mrow + mt*16 + a_row_l) * 48 + a_k_l * 2;
            ldsm_x4(Ah[mt],  base + off);
            ldsm_x4(Al_[mt], base + 6144 + off);
        }
        #pragma unroll
        for (int nb = 0; nb < 3; nb++) {       // Bh fragments
            uint32_t r4[4];
            ldsm_x4(r4, base + 12288 + (ncol + nb*16 + b_n_l) * 48 + b_k_l * 2);
            Bf[nb*2][0] = r4[0]; Bf[nb*2][1] = r4[1];
            Bf[nb*2+1][0] = r4[2]; Bf[nb*2+1][1] = r4[3];
        }
        #pragma unroll
        for (int mt = 0; mt < 2; mt++)
            #pragma unroll
            for (int nn = 0; nn < 6; nn++) {
                mma_bf16(acc[mt][nn], Ah[mt],  Bf[nn]);   // Ah*Bh
                mma_bf16(acc[mt][nn], Al_[mt], Bf[nn]);   // Al*Bh
            }
        #pragma unroll
        for (int nb = 0; nb < 3; nb++) {       // Bl fragments (reuse Bf)
            uint32_t r4[4];
            ldsm_x4(r4, base + 16896 + (ncol + nb*16 + b_n_l) * 48 + b_k_l * 2);
            Bf[nb*2][0] = r4[0]; Bf[nb*2][1] = r4[1];
            Bf[nb*2+1][0] = r4[2]; Bf[nb*2+1][1] = r4[3];
        }
        #pragma unroll
        for (int mt = 0; mt < 2; mt++)
            #pragma unroll
            for (int nn = 0; nn < 6; nn++)
                mma_bf16(acc[mt][nn], Ah[mt], Bf[nn]);    // Ah*Bl
        __syncthreads();
    }

    // ---- epilogue ----
    const int trow = lane >> 2, tcol = (lane & 3) * 2;
    #pragma unroll
    for (int mt = 0; mt < 2; mt++) {
        #pragma unroll
        for (int nn = 0; nn < 6; nn++) {
            int row0 = by*128 + mrow + mt*16 + trow;
            int col  = bx*96 + ncol + nn*8 + tcol;
            float b0 = bias[col], b1 = bias[col + 1];
            #pragma unroll
            for (int hh = 0; hh < 2; hh++) {
                int row = row0 + hh * 8;
                float v0 = acc[mt][nn][hh*2]   + b0;
                float v1 = acc[mt][nn][hh*2+1] + b1;
                size_t idx = (size_t)row * N + col;
                if (MODE == 1) { v0 += res[idx]; v1 += res[idx + 1]; }
                if (MODE == 2) {
                    split_store(Chi, Clo, idx,     gelu_exact(v0));
                    split_store(Chi, Clo, idx + 1, gelu_exact(v1));
                } else {
                    *(float2*)(Cf + idx) = make_float2(v0, v1);
                }
            }
        }
    }
}

// =====================================================================
// k_attn: per (head, window). fp32 f32x2; output -> bf16 hi/lo planes.
// =====================================================================
__global__ __launch_bounds__(128) void k_attn()
{
    __shared__ float QT[64][68];
    __shared__ float KT[64][68];
    __shared__ float VS[64][36];
    __shared__ float rsum[64];

    int hd = blockIdx.x, win = blockIdx.y, tid = threadIdx.x;
    int t0 = win * 64, qo = hd * 32;

    #pragma unroll
    for (int it = 0; it < 16; it++) {
        int flat = it * 128 + tid;
        int i = flat >> 5, c = flat & 31;
        size_t rq = (size_t)(t0 + i) * 576;
        size_t rb = (size_t)(t0 + i) * 384;
        QT[c][i]      = g_qkv[rq + qo + c];
        QT[32 + c][i] = g_bqk[rb + qo + c];
        KT[c][i]      = g_qkv[rq + 192 + qo + c];
        KT[32 + c][i] = g_bqk[rb + 192 + qo + c];
        VS[i][c]      = g_qkv[rq + 384 + qo + c];
    }
    __syncthreads();

    int tx = tid & 7, ty = tid >> 3;
    ull acc[4][4];
    #pragma unroll
    for (int r = 0; r < 4; r++)
        #pragma unroll
        for (int j = 0; j < 4; j++) acc[r][j] = 0ULL;

    #pragma unroll 4
    for (int cc = 0; cc < 64; cc++) {
        float4 a4 = *(const float4*)&QT[cc][ty*4];
        union { float4 f; ull u[2]; } u0, u1;
        u0.f = *(const float4*)&KT[cc][tx*8];
        u1.f = *(const float4*)&KT[cc][tx*8+4];
        float ar[4] = {a4.x, a4.y, a4.z, a4.w};
        #pragma unroll
        for (int r = 0; r < 4; r++) {
            ull a2 = pack2(ar[r]);
            fma2(acc[r][0], a2, u0.u[0]);
            fma2(acc[r][1], a2, u0.u[1]);
            fma2(acc[r][2], a2, u1.u[0]);
            fma2(acc[r][3], a2, u1.u[1]);
        }
    }
    __syncthreads();

    const float scale = 0.17677669529663687f;
    #pragma unroll
    for (int r = 0; r < 4; r++) {
        int i = ty*4 + r;
        #pragma unroll
        for (int jp = 0; jp < 4; jp++) {
            float2 v = unpack2(acc[r][jp]);
            int j = tx*8 + jp*2;
            QT[i][j]   = v.x * scale;
            QT[i][j+1] = v.y * scale;
        }
    }
    __syncthreads();

    {
        int i = tid >> 1, half = tid & 1;
        int m0 = half * 32;
        float mx = -1e30f;
        #pragma unroll
        for (int m = 0; m < 32; m++) mx = fmaxf(mx, QT[i][m0 + m]);
        mx = fmaxf(mx, __shfl_xor_sync(0xffffffffu, mx, 1));
        float sm = 0.f;
        #pragma unroll
        for (int m = 0; m < 32; m++) {
            float p = expf(QT[i][m0 + m] - mx);
            sm += p;
            KT[m0 + m][i] = p;
        }
        sm += __shfl_xor_sync(0xffffffffu, sm, 1);
        if (half == 0) rsum[i] = 1.0f / sm;
    }
    __syncthreads();

    ull oacc[4][2];
    #pragma unroll
    for (int r = 0; r < 4; r++) { oacc[r][0] = 0ULL; oacc[r][1] = 0ULL; }

    #pragma unroll 4
    for (int m = 0; m < 64; m++) {
        float4 a4 = *(const float4*)&KT[m][ty*4];
        union { float4 f; ull u[2]; } uv;
        uv.f = *(const float4*)&VS[m][tx*4];
        float ar[4] = {a4.x, a4.y, a4.z, a4.w};
        #pragma unroll
        for (int r = 0; r < 4; r++) {
            ull a2 = pack2(ar[r]);
            fma2(oacc[r][0], a2, uv.u[0]);
            fma2(oacc[r][1], a2, uv.u[1]);
        }
    }

    #pragma unroll
    for (int r = 0; r < 4; r++) {
        int i = ty*4 + r;
        float rs = rsum[i];
        size_t ob = (size_t)(t0 + i) * 192 + qo + tx*4;
        float2 v0 = unpack2(oacc[r][0]);
        float2 v1 = unpack2(oacc[r][1]);
        split_store(g_ath, g_atl, ob + 0, v0.x * rs);
        split_store(g_ath, g_atl, ob + 1, v0.y * rs);
        split_store(g_ath, g_atl, ob + 2, v1.x * rs);
        split_store(g_ath, g_atl, ob + 3, v1.y * rs);
    }
}

// =====================================================================
// k_ln2: LN(xh2) -> xn hi/lo planes
// =====================================================================
__global__ __launch_bounds__(256) void k_ln2(
    const float* __restrict__ w2, const float* __restrict__ b2)
{
    int t = blockIdx.x * 8 + (threadIdx.x >> 5);
    int lane = threadIdx.x & 31;
    const float* rp = g_xh2 + (size_t)t * DIMC;
    float v[6];
    float s = 0.f, sq = 0.f;
    #pragma unroll
    for (int k = 0; k < 6; k++) {
        v[k] = rp[lane + k*32];
        s += v[k]; sq += v[k]*v[k];
    }
    #pragma unroll
    for (int off = 16; off > 0; off >>= 1) {
        s  += __shfl_xor_sync(0xffffffffu, s,  off);
        sq += __shfl_xor_sync(0xffffffffu, sq, off);
    }
    float m = s * (1.0f/DIMC);
    float var = sq * (1.0f/DIMC) - m*m;
    float rstd = rsqrtf(var + 1e-5f);
    #pragma unroll
    for (int k = 0; k < 6; k++) {
        int c = lane + k*32;
        float o = (v[k] - m) * rstd * w2[c] + b2[c];
        split_store(g_xnh, g_xnl, (size_t)t * DIMC + c, o);
    }
}

// =====================================================================
// k_post: final (g_bqk reused as fp32 [T,192]) -> NCHW out
// =====================================================================
__global__ __launch_bounds__(256) void k_post(float* __restrict__ out)
{
    __shared__ float os[DIMC][33];
    int w0 = blockIdx.x * 32, h = blockIdx.y, b = blockIdx.z;
    int tid = threadIdx.x, lane = tid & 31, wrp = tid >> 5;
    int whh = h >> 3, r = h & 7;

    #pragma unroll
    for (int it = 0; it < 24; it++) {
        int flat = it * 256 + tid;
        int tokj = flat / 192, c = flat - tokj * 192;
        int w = w0 + tokj, ww = w >> 3, cp = w & 7;
        int trow = ((b*32 + whh)*32 + ww)*64 + r*8 + cp;
        os[c][tokj] = g_bqk[(size_t)trow*DIMC + c];
    }
    __syncthreads();
    #pragma unroll
    for (int it = 0; it < 24; it++) {
        int c = it * 8 + wrp;
        out[((size_t)(b*DIMC + c)*Hh + h)*Wc + w0 + lane] = os[c][lane];
    }
}

// =====================================================================
extern "C" void kernel_launch(void* const* d_in, const int* in_sizes, int n_in,
                              void* d_out, int out_size)
{
    const float* x     = (const float*)d_in[0];
    const float* bpe   = (const float*)d_in[1];
    const float* ln1w  = (const float*)d_in[2];
    const float* ln1b  = (const float*)d_in[3];
    const float* qkvw  = (const float*)d_in[4];
    const float* qkvb  = (const float*)d_in[5];
    const float* bpew  = (const float*)d_in[6];
    const float* bpeb  = (const float*)d_in[7];
    const float* projw = (const float*)d_in[8];
    const float* projb = (const float*)d_in[9];
    const float* ln2w  = (const float*)d_in[10];
    const float* ln2b  = (const float*)d_in[11];
    const float* fc1w  = (const float*)d_in[12];
    const float* fc1b  = (const float*)d_in[13];
    const float* fc2w  = (const float*)d_in[14];
    const float* fc2b  = (const float*)d_in[15];
    float* out = (float*)d_out;

    bf16 *wqh,*wql,*wbh,*wbl,*wph,*wpl,*w1h,*w1l,*w2h,*w2l;
    bf16 *xnh,*xnl,*bwh,*bwl,*ath,*atl,*h1h,*h1l;
    float *xres,*qkv,*bqk,*xh2;
    cudaGetSymbolAddress((void**)&wqh, g_wqh); cudaGetSymbolAddress((void**)&wql, g_wql);
    cudaGetSymbolAddress((void**)&wbh, g_wbh); cudaGetSymbolAddress((void**)&wbl, g_wbl);
    cudaGetSymbolAddress((void**)&wph, g_wph); cudaGetSymbolAddress((void**)&wpl, g_wpl);
    cudaGetSymbolAddress((void**)&w1h, g_w1h); cudaGetSymbolAddress((void**)&w1l, g_w1l);
    cudaGetSymbolAddress((void**)&w2h, g_w2h); cudaGetSymbolAddress((void**)&w2l, g_w2l);
    cudaGetSymbolAddress((void**)&xnh, g_xnh); cudaGetSymbolAddress((void**)&xnl, g_xnl);
    cudaGetSymbolAddress((void**)&bwh, g_bwh); cudaGetSymbolAddress((void**)&bwl, g_bwl);
    cudaGetSymbolAddress((void**)&ath, g_ath); cudaGetSymbolAddress((void**)&atl, g_atl);
    cudaGetSymbolAddress((void**)&h1h, g_h1h); cudaGetSymbolAddress((void**)&h1l, g_h1l);
    cudaGetSymbolAddress((void**)&xres, g_xres);
    cudaGetSymbolAddress((void**)&qkv,  g_qkv);
    cudaGetSymbolAddress((void**)&bqk,  g_bqk);
    cudaGetSymbolAddress((void**)&xh2,  g_xh2);

    dim3 wtb(32, 8);
    k_wt<<<dim3(576/32, 192/32), wtb>>>(qkvw, wqh, wql, 192, 576);
    k_wt<<<dim3(384/32,  32/32), wtb>>>(bpew, wbh, wbl,  32, 384);
    k_wt<<<dim3(192/32, 192/32), wtb>>>(projw, wph, wpl, 192, 192);
    k_wt<<<dim3(768/32, 192/32), wtb>>>(fc1w, w1h, w1l, 192, 768);
    k_wt<<<dim3(192/32, 768/32), wtb>>>(fc2w, w2h, w2l, 768, 192);

    // 1. transpose + LN1 (-> hi/lo) + bpe (-> hi/lo)
    k_pre<<<dim3(Wc/32, Hh, Bb), 256>>>(x, bpe, ln1w, ln1b);
    // 2. qkv = xn @ qkv_w + b  -> fp32 [T,576]
    k_hmma<0><<<dim3(576/96, TTOT/128), 256, SMEM_HM>>>(xnh, xnl, wqh, wql, qkvb, nullptr, qkv, nullptr, nullptr, 576, 192);
    // 3. bqk = bw @ bpe_w + b  -> fp32 [T,384]
    k_hmma<0><<<dim3(384/96, TTOT/128), 256, SMEM_HM>>>(bwh, bwl, wbh, wbl, bpeb, nullptr, bqk, nullptr, nullptr, 384, 32);
    // 4. attention -> attn hi/lo
    k_attn<<<dim3(NHEAD, NWIN), 128>>>();
    // 5. xh2 = attn @ proj_w + b + shortcut  -> fp32 [T,192]
    k_hmma<1><<<dim3(192/96, TTOT/128), 256, SMEM_HM>>>(ath, atl, wph, wpl, projb, xres, xh2, nullptr, nullptr, 192, 192);
    // 6. LN2 -> xn hi/lo
    k_ln2<<<TTOT/8, 256>>>(ln2w, ln2b);
    // 7. h1 = gelu(xn @ fc1_w + b)  -> bf16 hi/lo [T,768]
    k_hmma<2><<<dim3(768/96, TTOT/128), 256, SMEM_HM>>>(xnh, xnl, w1h, w1l, fc1b, nullptr, nullptr, h1h, h1l, 768, 192);
    // 8. final = h1 @ fc2_w + b + xh2  -> fp32 (reuse g_bqk)
    k_hmma<1><<<dim3(192/96, TTOT/128), 256, SMEM_HM>>>(h1h, h1l, w2h, w2l, fc2b, xh2, bqk, nullptr, nullptr, 192, 768);
    // 9. window layout -> NCHW
    k_post<<<dim3(Wc/32, Hh, Bb), 256>>>(out);
}